// round 10
// baseline (speedup 1.0000x reference)
#include <cuda_runtime.h>
#include <cuda_fp16.h>
#include <math.h>
#include <stdint.h>

#define NN 100000
#define GG 64
#define ASSETS 50
#define EMAX 1600000
#define NSCANB 128

// ---------------- scratch (device globals; no runtime allocation) ----------
__device__ __half2 g_xh [(size_t)NN * 32];   // 12.8 MB (x fp16)
__device__ __half2 g_h1h[(size_t)NN * 64];   // 25.6 MB (h1 fp16)
__device__ float g_sums[GG * 128];
__device__ int   g_gstart[GG];
__device__ int   g_gend[GG];
// CSR scratch
__device__ int g_deg[NN];
__device__ int g_off[NN + 1];
__device__ int g_cur[NN];
__device__ int g_sedge[EMAX];
// one-pass scan state (reset every launch by init_kernel)
__device__ int g_flags[NSCANB];
__device__ int g_aggs [NSCANB];
__device__ int g_prefs[NSCANB];

// ---------------- helpers ---------------------------------------------------
__device__ __forceinline__ void mma16(float* d, const uint32_t* a, const uint32_t* b) {
    asm volatile("mma.sync.aligned.m16n8k16.row.col.f32.f16.f16.f32 "
                 "{%0,%1,%2,%3}, {%4,%5,%6,%7}, {%8,%9}, {%0,%1,%2,%3};"
                 : "+f"(d[0]), "+f"(d[1]), "+f"(d[2]), "+f"(d[3])
                 : "r"(a[0]), "r"(a[1]), "r"(a[2]), "r"(a[3]),
                   "r"(b[0]), "r"(b[1]));
}

// ---------------- init: zero scratch + convert x -> fp16 ---------------------
__global__ void init_kernel(const float2* __restrict__ x, int n2, int N) {
    int i = blockIdx.x * blockDim.x + threadIdx.x;
    int stride = gridDim.x * blockDim.x;
    for (int j = i; j < n2; j += stride)
        g_xh[j] = __float22half2_rn(x[j]);
    for (int j = i; j < N; j += stride)
        g_deg[j] = 0;
    if (i < GG * 128) g_sums[i] = 0.f;
    if (i < GG) { g_gstart[i] = 0; g_gend[i] = 0; }
    if (i < NSCANB) { g_flags[i] = 0; g_aggs[i] = 0; g_prefs[i] = 0; }
}

// ---------------- CSR build --------------------------------------------------
__global__ void hist_kernel(const int* __restrict__ dst, int E) {
    int i = blockIdx.x * blockDim.x + threadIdx.x;
    if (i < E) atomicAdd(&g_deg[dst[i]], 1);
}

// single-pass exclusive scan with decoupled lookback.
// grid = ceil(n/1024) blocks (<=98, all resident on 148 SMs -> no deadlock).
// Also writes g_cur and detects per-graph boundaries in sorted batch.
__global__ void scan_onepass(int n, int E, const int* __restrict__ batch) {
    __shared__ int sh[256];
    __shared__ int s_base;
    int t = threadIdx.x;
    int bid = blockIdx.x;
    int base = bid * 1024 + t * 4;
    int v[4];
    #pragma unroll
    for (int i = 0; i < 4; i++) v[i] = (base + i < n) ? g_deg[base + i] : 0;
    int tsum = v[0] + v[1] + v[2] + v[3];
    sh[t] = tsum;
    __syncthreads();
    #pragma unroll
    for (int o = 1; o < 256; o <<= 1) {
        int x = (t >= o) ? sh[t - o] : 0;
        __syncthreads();
        sh[t] += x;
        __syncthreads();
    }
    int excl = sh[t] - tsum;

    if (t == 255) {
        int total = sh[255];
        if (bid == 0) {
            g_prefs[0] = total;
            __threadfence();
            atomicExch(&g_flags[0], 2);
            s_base = 0;
        } else {
            g_aggs[bid] = total;
            __threadfence();
            atomicExch(&g_flags[bid], 1);
            int run = 0;
            int i = bid - 1;
            while (true) {
                int f;
                do { f = atomicAdd(&g_flags[i], 0); } while (f == 0);
                __threadfence();
                if (f == 2) { run += g_prefs[i]; break; }
                run += g_aggs[i];
                i--;
            }
            g_prefs[bid] = run + total;
            __threadfence();
            atomicExch(&g_flags[bid], 2);
            s_base = run;
        }
    }
    __syncthreads();
    int run = excl + s_base;
    #pragma unroll
    for (int i = 0; i < 4; i++) {
        int idx = base + i;
        if (idx < n) {
            g_off[idx] = run;
            g_cur[idx] = run;
            int b = batch[idx];
            if (idx == 0 || batch[idx - 1] != b) g_gstart[b] = idx;
            if (idx == n - 1 || batch[idx + 1] != b) g_gend[b] = idx + 1;
            run += v[i];
        }
    }
    if (bid == 0 && t == 0) g_off[n] = E;
}

__global__ void fill_csr(const int* __restrict__ src, const int* __restrict__ dst, int E) {
    int i = blockIdx.x * blockDim.x + threadIdx.x;
    if (i < E) {
        int slot = atomicAdd(&g_cur[dst[i]], 1);
        g_sedge[slot] = src[i];
    }
}

// ---------------- fused gather + dual GEMM + bias + relu (+pool) -------------
// out[n][c] = relu( (sum_{j->n} feat[j]) @ wRel + feat[n] @ wRoot + bias )[c]
// A rows (agg) are gathered from CSR inside staging; B rows are feat[n].
// POOL=true: epilogue does segmented mean-pool into g_sums instead of storing.
template<int K, bool POOL>
__global__ void __launch_bounds__(256)
gemm_fused(const __half* __restrict__ feat,
           const float* __restrict__ wRel, const float* __restrict__ wRoot,
           const float* __restrict__ bias, __half2* __restrict__ out,
           const int* __restrict__ batch, int N, int num_tiles) {
    constexpr int U = K + 4;               // row stride in uint32
    extern __shared__ uint32_t smem_u[];
    uint32_t* sW  = smem_u;                // [128][U]
    uint32_t* sIn = smem_u + 128 * U;      // [64][U]
    float*    sInF = (float*)sIn;          // aliased fp32 tile for pooling
    __shared__ int sb[64];

    const int tid  = threadIdx.x;
    const int lane = tid & 31;
    const int wid  = tid >> 5;
    const int wm   = wid & 1;
    const int wn   = wid >> 1;
    const uint32_t* featu = (const uint32_t*)feat;

    // stage weights once: fp32 gmem -> fp16 smem, transposed n-major
    {
        __half* sWh = (__half*)sW;
        for (int idx = tid; idx < K * 128; idx += 256) {
            int k = idx >> 7;
            int n = idx & 127;
            sWh[n * (2 * U) + k]     = __float2half_rn(wRel[idx]);
            sWh[n * (2 * U) + K + k] = __float2half_rn(wRoot[idx]);
        }
    }

    const int fr = lane >> 2;
    const int fc = lane & 3;

    for (int tile = blockIdx.x; tile < num_tiles; tile += gridDim.x) {
        const int row0 = tile << 6;
        __syncthreads();   // sIn free (prev mma / weights staged)

        // ---- stage: warp w handles rows [w*8, w*8+8) ----
        {
            int r0w = wid * 8;
            for (int rr = 0; rr < 8; rr++) {
                int r = r0w + rr;
                int grow = row0 + r;
                if constexpr (K == 64) {
                    if (grow < N) {
                        // B: root feature row (32 uint32)
                        sIn[r * U + 32 + lane] = featu[(size_t)grow * 32 + lane];
                        // A: CSR gather, MLP=8
                        int beg = g_off[grow], end = g_off[grow + 1];
                        float2 a0 = make_float2(0.f, 0.f), a1 = a0, a2 = a0, a3 = a0;
                        float2 a4 = a0, a5 = a0, a6 = a0, a7 = a0;
                        for (int b = beg; b < end; b += 32) {
                            int m = min(32, end - b);
                            int s = (lane < m) ? g_sedge[b + lane] : 0;
                            int i = 0;
                            for (; i + 8 <= m; i += 8) {
                                int t0 = __shfl_sync(0xffffffffu, s, i);
                                int t1 = __shfl_sync(0xffffffffu, s, i + 1);
                                int t2 = __shfl_sync(0xffffffffu, s, i + 2);
                                int t3 = __shfl_sync(0xffffffffu, s, i + 3);
                                int t4 = __shfl_sync(0xffffffffu, s, i + 4);
                                int t5 = __shfl_sync(0xffffffffu, s, i + 5);
                                int t6 = __shfl_sync(0xffffffffu, s, i + 6);
                                int t7 = __shfl_sync(0xffffffffu, s, i + 7);
                                float2 v0 = __half22float2(g_xh[0 * 0 + (size_t)t0 * 32 + lane] * __half2(__float2half(1.f), __float2half(1.f)));
                                // (placeholder removed below)
                                (void)v0;
                                float2 w0 = __half22float2(((const __half2*)featu)[(size_t)t0 * 32 + lane]);
                                float2 w1 = __half22float2(((const __half2*)featu)[(size_t)t1 * 32 + lane]);
                                float2 w2 = __half22float2(((const __half2*)featu)[(size_t)t2 * 32 + lane]);
                                float2 w3 = __half22float2(((const __half2*)featu)[(size_t)t3 * 32 + lane]);
                                float2 w4 = __half22float2(((const __half2*)featu)[(size_t)t4 * 32 + lane]);
                                float2 w5 = __half22float2(((const __half2*)featu)[(size_t)t5 * 32 + lane]);
                                float2 w6 = __half22float2(((const __half2*)featu)[(size_t)t6 * 32 + lane]);
                                float2 w7 = __half22float2(((const __half2*)featu)[(size_t)t7 * 32 + lane]);
                                a0.x += w0.x; a0.y += w0.y;  a1.x += w1.x; a1.y += w1.y;
                                a2.x += w2.x; a2.y += w2.y;  a3.x += w3.x; a3.y += w3.y;
                                a4.x += w4.x; a4.y += w4.y;  a5.x += w5.x; a5.y += w5.y;
                                a6.x += w6.x; a6.y += w6.y;  a7.x += w7.x; a7.y += w7.y;
                            }
                            for (; i + 2 <= m; i += 2) {
                                int t0 = __shfl_sync(0xffffffffu, s, i);
                                int t1 = __shfl_sync(0xffffffffu, s, i + 1);
                                float2 w0 = __half22float2(((const __half2*)featu)[(size_t)t0 * 32 + lane]);
                                float2 w1 = __half22float2(((const __half2*)featu)[(size_t)t1 * 32 + lane]);
                                a0.x += w0.x; a0.y += w0.y;  a1.x += w1.x; a1.y += w1.y;
                            }
                            if (i < m) {
                                int t0 = __shfl_sync(0xffffffffu, s, i);
                                float2 w0 = __half22float2(((const __half2*)featu)[(size_t)t0 * 32 + lane]);
                                a0.x += w0.x; a0.y += w0.y;
                            }
                        }
                        float2 rs;
                        rs.x = ((a0.x + a1.x) + (a2.x + a3.x)) + ((a4.x + a5.x) + (a6.x + a7.x));
                        rs.y = ((a0.y + a1.y) + (a2.y + a3.y)) + ((a4.y + a5.y) + (a6.y + a7.y));
                        __half2 h = __float22half2_rn(rs);
                        sIn[r * U + lane] = *(uint32_t*)&h;
                    } else {
                        sIn[r * U + lane] = 0u;
                        sIn[r * U + 32 + lane] = 0u;
                    }
                } else {
                    if (grow < N) {
                        // B: root feature row (64 uint32 = 32 uint2)
                        ((uint2*)&sIn[r * U + 64])[lane] =
                            ((const uint2*)(featu + (size_t)grow * 64))[lane];
                        // A: CSR gather, MLP=8
                        int beg = g_off[grow], end = g_off[grow + 1];
                        float4 a0 = make_float4(0.f, 0.f, 0.f, 0.f);
                        float4 a1 = a0, a2 = a0, a3 = a0, a4 = a0, a5 = a0, a6 = a0, a7 = a0;
                        const uint2* f2 = (const uint2*)featu;
                        auto addin = [&](float4& acc, uint2 u) {
                            float2 lo = __half22float2(*(__half2*)&u.x);
                            float2 hi = __half22float2(*(__half2*)&u.y);
                            acc.x += lo.x; acc.y += lo.y; acc.z += hi.x; acc.w += hi.y;
                        };
                        for (int b = beg; b < end; b += 32) {
                            int m = min(32, end - b);
                            int s = (lane < m) ? g_sedge[b + lane] : 0;
                            int i = 0;
                            for (; i + 8 <= m; i += 8) {
                                int t0 = __shfl_sync(0xffffffffu, s, i);
                                int t1 = __shfl_sync(0xffffffffu, s, i + 1);
                                int t2 = __shfl_sync(0xffffffffu, s, i + 2);
                                int t3 = __shfl_sync(0xffffffffu, s, i + 3);
                                int t4 = __shfl_sync(0xffffffffu, s, i + 4);
                                int t5 = __shfl_sync(0xffffffffu, s, i + 5);
                                int t6 = __shfl_sync(0xffffffffu, s, i + 6);
                                int t7 = __shfl_sync(0xffffffffu, s, i + 7);
                                uint2 u0 = f2[(size_t)t0 * 32 + lane];
                                uint2 u1 = f2[(size_t)t1 * 32 + lane];
                                uint2 u2 = f2[(size_t)t2 * 32 + lane];
                                uint2 u3 = f2[(size_t)t3 * 32 + lane];
                                uint2 u4 = f2[(size_t)t4 * 32 + lane];
                                uint2 u5 = f2[(size_t)t5 * 32 + lane];
                                uint2 u6 = f2[(size_t)t6 * 32 + lane];
                                uint2 u7 = f2[(size_t)t7 * 32 + lane];
                                addin(a0, u0); addin(a1, u1); addin(a2, u2); addin(a3, u3);
                                addin(a4, u4); addin(a5, u5); addin(a6, u6); addin(a7, u7);
                            }
                            for (; i + 2 <= m; i += 2) {
                                int t0 = __shfl_sync(0xffffffffu, s, i);
                                int t1 = __shfl_sync(0xffffffffu, s, i + 1);
                                uint2 u0 = f2[(size_t)t0 * 32 + lane];
                                uint2 u1 = f2[(size_t)t1 * 32 + lane];
                                addin(a0, u0); addin(a1, u1);
                            }
                            if (i < m) {
                                int t0 = __shfl_sync(0xffffffffu, s, i);
                                uint2 u0 = f2[(size_t)t0 * 32 + lane];
                                addin(a0, u0);
                            }
                        }
                        float4 rs;
                        rs.x = ((a0.x + a1.x) + (a2.x + a3.x)) + ((a4.x + a5.x) + (a6.x + a7.x));
                        rs.y = ((a0.y + a1.y) + (a2.y + a3.y)) + ((a4.y + a5.y) + (a6.y + a7.y));
                        rs.z = ((a0.z + a1.z) + (a2.z + a3.z)) + ((a4.z + a5.z) + (a6.z + a7.z));
                        rs.w = ((a0.w + a1.w) + (a2.w + a3.w)) + ((a4.w + a5.w) + (a6.w + a7.w));
                        uint2 o;
                        *(__half2*)&o.x = __float22half2_rn(make_float2(rs.x, rs.y));
                        *(__half2*)&o.y = __float22half2_rn(make_float2(rs.z, rs.w));
                        ((uint2*)&sIn[r * U])[lane] = o;
                    } else {
                        uint2 z = make_uint2(0u, 0u);
                        ((uint2*)&sIn[r * U])[lane] = z;
                        ((uint2*)&sIn[r * U + 64])[lane] = z;
                    }
                }
            }
        }
        __syncthreads();

        // ---- mma ----
        float acc[2][4][4] = {};
        {
            const uint32_t* sInW = sIn + (wm * 32) * U;
            const uint32_t* sWW  = sW  + (wn * 32) * U;
            #pragma unroll 4
            for (int kw = 0; kw < K; kw += 8) {
                uint32_t a[2][4];
                #pragma unroll
                for (int mt = 0; mt < 2; mt++) {
                    const uint32_t* p = sInW + (mt * 16 + fr) * U + kw + fc;
                    a[mt][0] = p[0];
                    a[mt][1] = p[8 * U];
                    a[mt][2] = p[4];
                    a[mt][3] = p[8 * U + 4];
                }
                uint32_t b[4][2];
                #pragma unroll
                for (int nt = 0; nt < 4; nt++) {
                    const uint32_t* p = sWW + (nt * 8 + fr) * U + kw + fc;
                    b[nt][0] = p[0];
                    b[nt][1] = p[4];
                }
                #pragma unroll
                for (int mt = 0; mt < 2; mt++)
                    #pragma unroll
                    for (int nt = 0; nt < 4; nt++)
                        mma16(acc[mt][nt], a[mt], b[nt]);
            }
        }

        // ---- epilogue ----
        if (POOL) {
            __syncthreads();   // everyone done reading sIn before overwrite
            if (tid < 64) {
                int rr = row0 + tid;
                sb[tid] = (rr < N) ? batch[rr] : -1;
            }
            #pragma unroll
            for (int mt = 0; mt < 2; mt++) {
                int lr = wm * 32 + mt * 16 + fr;
                #pragma unroll
                for (int nt = 0; nt < 4; nt++) {
                    int col = wn * 32 + nt * 8 + 2 * fc;
                    float2 bb = *(const float2*)&bias[col];
                    float2 o0, o1;
                    o0.x = fmaxf(acc[mt][nt][0] + bb.x, 0.f);
                    o0.y = fmaxf(acc[mt][nt][1] + bb.y, 0.f);
                    o1.x = fmaxf(acc[mt][nt][2] + bb.x, 0.f);
                    o1.y = fmaxf(acc[mt][nt][3] + bb.y, 0.f);
                    *(float2*)&sInF[lr * 130 + col]       = o0;
                    *(float2*)&sInF[(lr + 8) * 130 + col] = o1;
                }
            }
            __syncthreads();
            {
                int m = min(64, N - row0);
                int col  = tid & 127;
                int half = tid >> 7;
                int rs = half * 32;
                int re = min(m, rs + 32);
                if (rs < re) {
                    float acs = 0.f;
                    int cur = sb[rs];
                    for (int r = rs; r < re; r++) {
                        int g = sb[r];
                        float v = sInF[r * 130 + col];
                        if (g != cur) {
                            atomicAdd(&g_sums[cur * 128 + col], acs);
                            acs = 0.f; cur = g;
                        }
                        acs += v;
                    }
                    atomicAdd(&g_sums[cur * 128 + col], acs);
                }
            }
        } else {
            #pragma unroll
            for (int mt = 0; mt < 2; mt++) {
                int r1 = row0 + wm * 32 + mt * 16 + fr;
                #pragma unroll
                for (int nt = 0; nt < 4; nt++) {
                    int col = wn * 32 + nt * 8 + 2 * fc;
                    float2 bb = *(const float2*)&bias[col];
                    if (r1 < N) {
                        float2 o;
                        o.x = fmaxf(acc[mt][nt][0] + bb.x, 0.f);
                        o.y = fmaxf(acc[mt][nt][1] + bb.y, 0.f);
                        out[(size_t)r1 * 64 + (col >> 1)] = __float22half2_rn(o);
                    }
                    if (r1 + 8 < N) {
                        float2 o;
                        o.x = fmaxf(acc[mt][nt][2] + bb.x, 0.f);
                        o.y = fmaxf(acc[mt][nt][3] + bb.y, 0.f);
                        out[(size_t)(r1 + 8) * 64 + (col >> 1)] = __float22half2_rn(o);
                    }
                }
            }
        }
    }
}

// ---------------- MLP head + softmax (one block per graph) -------------------
__global__ void head_kernel(const float* __restrict__ fc1w, const float* __restrict__ fc1b,
                            const float* __restrict__ fc2w, const float* __restrict__ fc2b,
                            float* __restrict__ out) {
    __shared__ float p[128];
    __shared__ float hdn[128];
    __shared__ float lg[ASSETS];
    __shared__ float smax, ssum;
    int g = blockIdx.x, t = threadIdx.x;

    float cnt = fmaxf((float)(g_gend[g] - g_gstart[g]), 1.f);
    p[t] = g_sums[g * 128 + t] / cnt;
    __syncthreads();

    float a = fc1b[t];
    #pragma unroll 8
    for (int k = 0; k < 128; k++) a = fmaf(p[k], fc1w[k * 128 + t], a);
    hdn[t] = fmaxf(a, 0.f);
    __syncthreads();

    float logit = 0.f;
    if (t < ASSETS) {
        logit = fc2b[t];
        #pragma unroll 8
        for (int k = 0; k < 128; k++) logit = fmaf(hdn[k], fc2w[k * ASSETS + t], logit);
        lg[t] = logit;
    }
    __syncthreads();
    if (t == 0) {
        float m = -1e30f;
        for (int i = 0; i < ASSETS; i++) m = fmaxf(m, lg[i]);
        smax = m;
    }
    __syncthreads();
    float e = 0.f;
    if (t < ASSETS) { e = expf(logit - smax); lg[t] = e; }
    __syncthreads();
    if (t == 0) {
        float s = 0.f;
        for (int i = 0; i < ASSETS; i++) s += lg[i];
        ssum = s;
    }
    __syncthreads();
    if (t < ASSETS) out[g * ASSETS + t] = lg[t] / ssum;
}

// ---------------- launch -----------------------------------------------------
extern "C" void kernel_launch(void* const* d_in, const int* in_sizes, int n_in,
                              void* d_out, int out_size) {
    const float* x       = (const float*)d_in[0];
    const int*   ei      = (const int*)d_in[1];
    const int*   batch   = (const int*)d_in[2];
    const float* w1_rel  = (const float*)d_in[3];
    const float* b1      = (const float*)d_in[4];
    const float* w1_root = (const float*)d_in[5];
    const float* w2_rel  = (const float*)d_in[6];
    const float* b2      = (const float*)d_in[7];
    const float* w2_root = (const float*)d_in[8];
    const float* fc1w    = (const float*)d_in[9];
    const float* fc1b    = (const float*)d_in[10];
    const float* fc2w    = (const float*)d_in[11];
    const float* fc2b    = (const float*)d_in[12];
    float*       out     = (float*)d_out;

    const int N = in_sizes[2];        // 100000
    const int E = in_sizes[1] / 2;    // 1600000
    const int* src = ei;
    const int* dst = ei + E;

    void *xh, *h1h;
    cudaGetSymbolAddress(&xh,  g_xh);
    cudaGetSymbolAddress(&h1h, g_h1h);

    const int SMEM1 = 192 * (64  + 4) * 4;   // 52224 B
    const int SMEM2 = 192 * (128 + 4) * 4;   // 101376 B
    cudaFuncSetAttribute((const void*)gemm_fused<64, false>,
                         cudaFuncAttributeMaxDynamicSharedMemorySize, SMEM1);
    cudaFuncSetAttribute((const void*)gemm_fused<128, true>,
                         cudaFuncAttributeMaxDynamicSharedMemorySize, SMEM2);

    // ---- init + CSR build ----
    init_kernel<<<512, 256>>>((const float2*)x, N * 32, N);
    hist_kernel<<<(E + 255) / 256, 256>>>(dst, E);
    int nscan = (N + 1023) / 1024;
    scan_onepass<<<nscan, 256>>>(N, E, batch);
    fill_csr<<<(E + 255) / 256, 256>>>(src, dst, E);

    int tiles = (N + 63) / 64;
    int grid = tiles < 296 ? tiles : 296;

    // ---- layer 1: fused gather + dual GEMM -> h1 (fp16) ----
    gemm_fused<64, false><<<grid, 256, SMEM1>>>(
        (const __half*)xh, w1_rel, w1_root, b1,
        (__half2*)h1h, nullptr, N, tiles);

    // ---- layer 2: fused gather + dual GEMM + mean-pool ----
    gemm_fused<128, true><<<grid, 256, SMEM2>>>(
        (const __half*)h1h, w2_rel, w2_root, b2,
        nullptr, batch, N, tiles);

    // ---- head ----
    head_kernel<<<GG, 128>>>(fc1w, fc1b, fc2w, fc2b, out);
}

// round 11
// speedup vs baseline: 1.5083x; 1.5083x over previous
#include <cuda_runtime.h>
#include <cuda_fp16.h>
#include <math.h>
#include <stdint.h>

#define NN 100000
#define GG 64
#define ASSETS 50
#define EMAX 1600000
#define NSCANB 128

// ---------------- scratch (device globals; no runtime allocation) ----------
__device__ __half2 g_xh   [(size_t)NN * 32];   // 12.8 MB (x fp16)
__device__ __half2 g_agg1h[(size_t)NN * 32];   // 12.8 MB (agg1 fp16)
__device__ __half2 g_h1h  [(size_t)NN * 64];   // 25.6 MB (h1 fp16)
__device__ __half2 g_agg2h[(size_t)NN * 64];   // 25.6 MB (agg2 fp16)
__device__ float g_sums[GG * 128];
__device__ int   g_gstart[GG];
__device__ int   g_gend[GG];
// CSR scratch
__device__ int g_deg[NN];
__device__ int g_off[NN + 1];
__device__ int g_cur[NN];
__device__ int g_sedge[EMAX];
// one-pass scan state (reset every launch by init_kernel)
__device__ int g_flags[NSCANB];
__device__ int g_aggs [NSCANB];
__device__ int g_prefs[NSCANB];

// ---------------- helpers ---------------------------------------------------
__device__ __forceinline__ void mma16(float* d, const uint32_t* a, const uint32_t* b) {
    asm volatile("mma.sync.aligned.m16n8k16.row.col.f32.f16.f16.f32 "
                 "{%0,%1,%2,%3}, {%4,%5,%6,%7}, {%8,%9}, {%0,%1,%2,%3};"
                 : "+f"(d[0]), "+f"(d[1]), "+f"(d[2]), "+f"(d[3])
                 : "r"(a[0]), "r"(a[1]), "r"(a[2]), "r"(a[3]),
                   "r"(b[0]), "r"(b[1]));
}

// ---------------- init: zero scratch + convert x -> fp16 ---------------------
__global__ void init_kernel(const float2* __restrict__ x, int n2, int N) {
    int i = blockIdx.x * blockDim.x + threadIdx.x;
    int stride = gridDim.x * blockDim.x;
    for (int j = i; j < n2; j += stride)
        g_xh[j] = __float22half2_rn(x[j]);
    for (int j = i; j < N; j += stride)
        g_deg[j] = 0;
    if (i < GG * 128) g_sums[i] = 0.f;
    if (i < GG) { g_gstart[i] = 0; g_gend[i] = 0; }
    if (i < NSCANB) { g_flags[i] = 0; g_aggs[i] = 0; g_prefs[i] = 0; }
}

// ---------------- CSR build --------------------------------------------------
__global__ void hist_kernel(const int* __restrict__ dst, int E) {
    int i = blockIdx.x * blockDim.x + threadIdx.x;
    if (i < E) atomicAdd(&g_deg[dst[i]], 1);
}

// single-pass exclusive scan with decoupled lookback.
// grid = ceil(n/1024) <= 98 blocks, all resident -> no deadlock.
// Also writes g_cur and detects per-graph boundaries in sorted batch.
__global__ void scan_onepass(int n, int E, const int* __restrict__ batch) {
    __shared__ int sh[256];
    __shared__ int s_base;
    int t = threadIdx.x;
    int bid = blockIdx.x;
    int base = bid * 1024 + t * 4;
    int v[4];
    #pragma unroll
    for (int i = 0; i < 4; i++) v[i] = (base + i < n) ? g_deg[base + i] : 0;
    int tsum = v[0] + v[1] + v[2] + v[3];
    sh[t] = tsum;
    __syncthreads();
    #pragma unroll
    for (int o = 1; o < 256; o <<= 1) {
        int x = (t >= o) ? sh[t - o] : 0;
        __syncthreads();
        sh[t] += x;
        __syncthreads();
    }
    int excl = sh[t] - tsum;

    if (t == 255) {
        int total = sh[255];
        if (bid == 0) {
            g_prefs[0] = total;
            __threadfence();
            atomicExch(&g_flags[0], 2);
            s_base = 0;
        } else {
            g_aggs[bid] = total;
            __threadfence();
            atomicExch(&g_flags[bid], 1);
            int run = 0;
            int i = bid - 1;
            while (true) {
                int f;
                do { f = atomicAdd(&g_flags[i], 0); } while (f == 0);
                __threadfence();
                if (f == 2) { run += g_prefs[i]; break; }
                run += g_aggs[i];
                i--;
            }
            g_prefs[bid] = run + total;
            __threadfence();
            atomicExch(&g_flags[bid], 2);
            s_base = run;
        }
    }
    __syncthreads();
    int run = excl + s_base;
    #pragma unroll
    for (int i = 0; i < 4; i++) {
        int idx = base + i;
        if (idx < n) {
            g_off[idx] = run;
            g_cur[idx] = run;
            int b = batch[idx];
            if (idx == 0 || batch[idx - 1] != b) g_gstart[b] = idx;
            if (idx == n - 1 || batch[idx + 1] != b) g_gend[b] = idx + 1;
            run += v[i];
        }
    }
    if (bid == 0 && t == 0) g_off[n] = E;
}

__global__ void fill_csr(const int* __restrict__ src, const int* __restrict__ dst, int E) {
    int i = blockIdx.x * blockDim.x + threadIdx.x;
    if (i < E) {
        int slot = atomicAdd(&g_cur[dst[i]], 1);
        g_sedge[slot] = src[i];
    }
}

// ---------------- CSR gather aggregation (fp16 in/out, fp32 acc, MLP=8) ------
__global__ void gather64h(int N) {
    int gtid = blockIdx.x * blockDim.x + threadIdx.x;
    int node = gtid >> 5;
    int lane = gtid & 31;
    if (node >= N) return;
    int beg = g_off[node];
    int end = g_off[node + 1];
    float2 a0 = make_float2(0.f, 0.f), a1 = a0, a2 = a0, a3 = a0;
    float2 a4 = a0, a5 = a0, a6 = a0, a7 = a0;
    for (int b = beg; b < end; b += 32) {
        int m = min(32, end - b);
        int s = (lane < m) ? g_sedge[b + lane] : 0;
        int i = 0;
        for (; i + 8 <= m; i += 8) {
            int t0 = __shfl_sync(0xffffffffu, s, i);
            int t1 = __shfl_sync(0xffffffffu, s, i + 1);
            int t2 = __shfl_sync(0xffffffffu, s, i + 2);
            int t3 = __shfl_sync(0xffffffffu, s, i + 3);
            int t4 = __shfl_sync(0xffffffffu, s, i + 4);
            int t5 = __shfl_sync(0xffffffffu, s, i + 5);
            int t6 = __shfl_sync(0xffffffffu, s, i + 6);
            int t7 = __shfl_sync(0xffffffffu, s, i + 7);
            float2 v0 = __half22float2(g_xh[(size_t)t0 * 32 + lane]);
            float2 v1 = __half22float2(g_xh[(size_t)t1 * 32 + lane]);
            float2 v2 = __half22float2(g_xh[(size_t)t2 * 32 + lane]);
            float2 v3 = __half22float2(g_xh[(size_t)t3 * 32 + lane]);
            float2 v4 = __half22float2(g_xh[(size_t)t4 * 32 + lane]);
            float2 v5 = __half22float2(g_xh[(size_t)t5 * 32 + lane]);
            float2 v6 = __half22float2(g_xh[(size_t)t6 * 32 + lane]);
            float2 v7 = __half22float2(g_xh[(size_t)t7 * 32 + lane]);
            a0.x += v0.x; a0.y += v0.y;  a1.x += v1.x; a1.y += v1.y;
            a2.x += v2.x; a2.y += v2.y;  a3.x += v3.x; a3.y += v3.y;
            a4.x += v4.x; a4.y += v4.y;  a5.x += v5.x; a5.y += v5.y;
            a6.x += v6.x; a6.y += v6.y;  a7.x += v7.x; a7.y += v7.y;
        }
        for (; i + 4 <= m; i += 4) {
            int t0 = __shfl_sync(0xffffffffu, s, i);
            int t1 = __shfl_sync(0xffffffffu, s, i + 1);
            int t2 = __shfl_sync(0xffffffffu, s, i + 2);
            int t3 = __shfl_sync(0xffffffffu, s, i + 3);
            float2 v0 = __half22float2(g_xh[(size_t)t0 * 32 + lane]);
            float2 v1 = __half22float2(g_xh[(size_t)t1 * 32 + lane]);
            float2 v2 = __half22float2(g_xh[(size_t)t2 * 32 + lane]);
            float2 v3 = __half22float2(g_xh[(size_t)t3 * 32 + lane]);
            a0.x += v0.x; a0.y += v0.y;  a1.x += v1.x; a1.y += v1.y;
            a2.x += v2.x; a2.y += v2.y;  a3.x += v3.x; a3.y += v3.y;
        }
        if (i + 2 <= m) {
            int t0 = __shfl_sync(0xffffffffu, s, i);
            int t1 = __shfl_sync(0xffffffffu, s, i + 1);
            float2 v0 = __half22float2(g_xh[(size_t)t0 * 32 + lane]);
            float2 v1 = __half22float2(g_xh[(size_t)t1 * 32 + lane]);
            a0.x += v0.x; a0.y += v0.y;  a1.x += v1.x; a1.y += v1.y;
            i += 2;
        }
        if (i < m) {
            int t0 = __shfl_sync(0xffffffffu, s, i);
            float2 v0 = __half22float2(g_xh[(size_t)t0 * 32 + lane]);
            a0.x += v0.x; a0.y += v0.y;
        }
    }
    float2 r;
    r.x = ((a0.x + a1.x) + (a2.x + a3.x)) + ((a4.x + a5.x) + (a6.x + a7.x));
    r.y = ((a0.y + a1.y) + (a2.y + a3.y)) + ((a4.y + a5.y) + (a6.y + a7.y));
    g_agg1h[(size_t)node * 32 + lane] = __float22half2_rn(r);
}

__global__ void gather128h(int N) {
    const uint2* feat = (const uint2*)g_h1h;
    int gtid = blockIdx.x * blockDim.x + threadIdx.x;
    int node = gtid >> 5;
    int lane = gtid & 31;
    if (node >= N) return;
    int beg = g_off[node];
    int end = g_off[node + 1];
    float4 a0 = make_float4(0.f, 0.f, 0.f, 0.f);
    float4 a1 = a0, a2 = a0, a3 = a0, a4 = a0, a5 = a0, a6 = a0, a7 = a0;

    auto addin = [&](float4& acc, uint2 u) {
        float2 lo = __half22float2(*(__half2*)&u.x);
        float2 hi = __half22float2(*(__half2*)&u.y);
        acc.x += lo.x; acc.y += lo.y; acc.z += hi.x; acc.w += hi.y;
    };

    for (int b = beg; b < end; b += 32) {
        int m = min(32, end - b);
        int s = (lane < m) ? g_sedge[b + lane] : 0;
        int i = 0;
        for (; i + 8 <= m; i += 8) {
            int t0 = __shfl_sync(0xffffffffu, s, i);
            int t1 = __shfl_sync(0xffffffffu, s, i + 1);
            int t2 = __shfl_sync(0xffffffffu, s, i + 2);
            int t3 = __shfl_sync(0xffffffffu, s, i + 3);
            int t4 = __shfl_sync(0xffffffffu, s, i + 4);
            int t5 = __shfl_sync(0xffffffffu, s, i + 5);
            int t6 = __shfl_sync(0xffffffffu, s, i + 6);
            int t7 = __shfl_sync(0xffffffffu, s, i + 7);
            uint2 u0 = feat[(size_t)t0 * 32 + lane];
            uint2 u1 = feat[(size_t)t1 * 32 + lane];
            uint2 u2 = feat[(size_t)t2 * 32 + lane];
            uint2 u3 = feat[(size_t)t3 * 32 + lane];
            uint2 u4 = feat[(size_t)t4 * 32 + lane];
            uint2 u5 = feat[(size_t)t5 * 32 + lane];
            uint2 u6 = feat[(size_t)t6 * 32 + lane];
            uint2 u7 = feat[(size_t)t7 * 32 + lane];
            addin(a0, u0); addin(a1, u1); addin(a2, u2); addin(a3, u3);
            addin(a4, u4); addin(a5, u5); addin(a6, u6); addin(a7, u7);
        }
        for (; i + 4 <= m; i += 4) {
            int t0 = __shfl_sync(0xffffffffu, s, i);
            int t1 = __shfl_sync(0xffffffffu, s, i + 1);
            int t2 = __shfl_sync(0xffffffffu, s, i + 2);
            int t3 = __shfl_sync(0xffffffffu, s, i + 3);
            uint2 u0 = feat[(size_t)t0 * 32 + lane];
            uint2 u1 = feat[(size_t)t1 * 32 + lane];
            uint2 u2 = feat[(size_t)t2 * 32 + lane];
            uint2 u3 = feat[(size_t)t3 * 32 + lane];
            addin(a0, u0); addin(a1, u1); addin(a2, u2); addin(a3, u3);
        }
        if (i + 2 <= m) {
            int t0 = __shfl_sync(0xffffffffu, s, i);
            int t1 = __shfl_sync(0xffffffffu, s, i + 1);
            uint2 u0 = feat[(size_t)t0 * 32 + lane];
            uint2 u1 = feat[(size_t)t1 * 32 + lane];
            addin(a0, u0); addin(a1, u1);
            i += 2;
        }
        if (i < m) {
            int t0 = __shfl_sync(0xffffffffu, s, i);
            uint2 u0 = feat[(size_t)t0 * 32 + lane];
            addin(a0, u0);
        }
    }
    float4 r;
    r.x = ((a0.x + a1.x) + (a2.x + a3.x)) + ((a4.x + a5.x) + (a6.x + a7.x));
    r.y = ((a0.y + a1.y) + (a2.y + a3.y)) + ((a4.y + a5.y) + (a6.y + a7.y));
    r.z = ((a0.z + a1.z) + (a2.z + a3.z)) + ((a4.z + a5.z) + (a6.z + a7.z));
    r.w = ((a0.w + a1.w) + (a2.w + a3.w)) + ((a4.w + a5.w) + (a6.w + a7.w));
    uint2 o;
    *(__half2*)&o.x = __float22half2_rn(make_float2(r.x, r.y));
    *(__half2*)&o.y = __float22half2_rn(make_float2(r.z, r.w));
    ((uint2*)g_agg2h)[(size_t)node * 32 + lane] = o;
}

// ---------------- fused dual GEMM (fp16 tensor cores) + bias + relu ----------
// POOL=true: epilogue does segmented mean-pool into g_sums (batch sorted).
template<int K, bool PF, bool POOL>
__global__ void __launch_bounds__(256)
gemm_dual_fp16(const __half* __restrict__ A, const __half* __restrict__ B,
               const float* __restrict__ wA, const float* __restrict__ wB,
               const float* __restrict__ bias, __half2* __restrict__ out,
               const int* __restrict__ batch, int N, int num_tiles) {
    constexpr int U   = K + 4;             // row stride in uint32
    constexpr int QP4 = K / 8;             // uint4 per row per matrix
    constexpr int PER = (64 * QP4) / 256;

    extern __shared__ uint32_t smem_u[];
    uint32_t* sW  = smem_u;                // [128][U]
    uint32_t* sIn = smem_u + 128 * U;      // [64][U]
    float*    sInF = (float*)sIn;          // aliased fp32 tile for pooling
    __shared__ int sb[64];

    const int tid  = threadIdx.x;
    const int lane = tid & 31;
    const int wid  = tid >> 5;
    const int wm   = wid & 1;
    const int wn   = wid >> 1;

    // stage weights once: fp32 gmem -> fp16 smem, transposed n-major
    {
        __half* sWh = (__half*)sW;
        for (int idx = tid; idx < K * 128; idx += 256) {
            int k = idx >> 7;
            int n = idx & 127;
            sWh[n * (2 * U) + k]     = __float2half_rn(wA[idx]);
            sWh[n * (2 * U) + K + k] = __float2half_rn(wB[idx]);
        }
    }

    uint4 pa[PER], pb[PER];

    auto loadTile = [&](int tile) {
        #pragma unroll
        for (int i = 0; i < PER; i++) {
            int idx = tid + i * 256;
            int r = idx / QP4, q = idx % QP4;
            int grow = tile * 64 + r;
            if (tile < num_tiles && grow < N) {
                pa[i] = ((const uint4*)(A + (size_t)grow * K))[q];
                pb[i] = ((const uint4*)(B + (size_t)grow * K))[q];
            } else {
                pa[i] = make_uint4(0u, 0u, 0u, 0u);
                pb[i] = pa[i];
            }
        }
    };
    auto storeTile = [&]() {
        #pragma unroll
        for (int i = 0; i < PER; i++) {
            int idx = tid + i * 256;
            int r = idx / QP4, q = idx % QP4;
            *(uint4*)&sIn[r * U + q * 4]            = pa[i];
            *(uint4*)&sIn[r * U + (K >> 1) + q * 4] = pb[i];
        }
    };

    loadTile(blockIdx.x);
    __syncthreads();
    storeTile();
    __syncthreads();

    const int fr = lane >> 2;
    const int fc = lane & 3;

    for (int tile = blockIdx.x; tile < num_tiles; tile += gridDim.x) {
        const int row0 = tile << 6;
        const int ntile = tile + gridDim.x;

        if (PF && ntile < num_tiles) loadTile(ntile);

        float acc[2][4][4] = {};
        const uint32_t* sInW = sIn + (wm * 32) * U;
        const uint32_t* sWW  = sW  + (wn * 32) * U;

        #pragma unroll 4
        for (int kw = 0; kw < K; kw += 8) {
            uint32_t a[2][4];
            #pragma unroll
            for (int mt = 0; mt < 2; mt++) {
                const uint32_t* p = sInW + (mt * 16 + fr) * U + kw + fc;
                a[mt][0] = p[0];
                a[mt][1] = p[8 * U];
                a[mt][2] = p[4];
                a[mt][3] = p[8 * U + 4];
            }
            uint32_t b[4][2];
            #pragma unroll
            for (int nt = 0; nt < 4; nt++) {
                const uint32_t* p = sWW + (nt * 8 + fr) * U + kw + fc;
                b[nt][0] = p[0];
                b[nt][1] = p[4];
            }
            #pragma unroll
            for (int mt = 0; mt < 2; mt++)
                #pragma unroll
                for (int nt = 0; nt < 4; nt++)
                    mma16(acc[mt][nt], a[mt], b[nt]);
        }

        __syncthreads();   // done reading sIn

        if (POOL) {
            if (tid < 64) {
                int rr = row0 + tid;
                sb[tid] = (rr < N) ? batch[rr] : -1;
            }
            #pragma unroll
            for (int mt = 0; mt < 2; mt++) {
                int lr = wm * 32 + mt * 16 + fr;
                #pragma unroll
                for (int nt = 0; nt < 4; nt++) {
                    int col = wn * 32 + nt * 8 + 2 * fc;
                    float2 bb = *(const float2*)&bias[col];
                    float2 o0, o1;
                    o0.x = fmaxf(acc[mt][nt][0] + bb.x, 0.f);
                    o0.y = fmaxf(acc[mt][nt][1] + bb.y, 0.f);
                    o1.x = fmaxf(acc[mt][nt][2] + bb.x, 0.f);
                    o1.y = fmaxf(acc[mt][nt][3] + bb.y, 0.f);
                    *(float2*)&sInF[lr * 130 + col]       = o0;
                    *(float2*)&sInF[(lr + 8) * 130 + col] = o1;
                }
            }
            __syncthreads();
            {
                int m = min(64, N - row0);
                int col  = tid & 127;
                int half = tid >> 7;
                int rs = half * 32;
                int re = min(m, rs + 32);
                if (rs < re) {
                    float acs = 0.f;
                    int cur = sb[rs];
                    for (int r = rs; r < re; r++) {
                        int g = sb[r];
                        float v = sInF[r * 130 + col];
                        if (g != cur) {
                            atomicAdd(&g_sums[cur * 128 + col], acs);
                            acs = 0.f; cur = g;
                        }
                        acs += v;
                    }
                    atomicAdd(&g_sums[cur * 128 + col], acs);
                }
            }
            __syncthreads();
            if (ntile < num_tiles) {
                if (!PF) loadTile(ntile);
                storeTile();
            }
            __syncthreads();
        } else {
            if (ntile < num_tiles) {
                if (!PF) loadTile(ntile);
                storeTile();
            }
            __syncthreads();
            #pragma unroll
            for (int mt = 0; mt < 2; mt++) {
                int r1 = row0 + wm * 32 + mt * 16 + fr;
                #pragma unroll
                for (int nt = 0; nt < 4; nt++) {
                    int col = wn * 32 + nt * 8 + 2 * fc;
                    float2 bb = *(const float2*)&bias[col];
                    if (r1 < N) {
                        float2 o;
                        o.x = fmaxf(acc[mt][nt][0] + bb.x, 0.f);
                        o.y = fmaxf(acc[mt][nt][1] + bb.y, 0.f);
                        out[(size_t)r1 * 64 + (col >> 1)] = __float22half2_rn(o);
                    }
                    if (r1 + 8 < N) {
                        float2 o;
                        o.x = fmaxf(acc[mt][nt][2] + bb.x, 0.f);
                        o.y = fmaxf(acc[mt][nt][3] + bb.y, 0.f);
                        out[(size_t)(r1 + 8) * 64 + (col >> 1)] = __float22half2_rn(o);
                    }
                }
            }
        }
    }
}

// ---------------- MLP head + softmax (one block per graph) -------------------
__global__ void head_kernel(const float* __restrict__ fc1w, const float* __restrict__ fc1b,
                            const float* __restrict__ fc2w, const float* __restrict__ fc2b,
                            float* __restrict__ out) {
    __shared__ float p[128];
    __shared__ float hdn[128];
    __shared__ float lg[ASSETS];
    __shared__ float smax, ssum;
    int g = blockIdx.x, t = threadIdx.x;

    float cnt = fmaxf((float)(g_gend[g] - g_gstart[g]), 1.f);
    p[t] = g_sums[g * 128 + t] / cnt;
    __syncthreads();

    float a = fc1b[t];
    #pragma unroll 8
    for (int k = 0; k < 128; k++) a = fmaf(p[k], fc1w[k * 128 + t], a);
    hdn[t] = fmaxf(a, 0.f);
    __syncthreads();

    float logit = 0.f;
    if (t < ASSETS) {
        logit = fc2b[t];
        #pragma unroll 8
        for (int k = 0; k < 128; k++) logit = fmaf(hdn[k], fc2w[k * ASSETS + t], logit);
        lg[t] = logit;
    }
    __syncthreads();
    if (t == 0) {
        float m = -1e30f;
        for (int i = 0; i < ASSETS; i++) m = fmaxf(m, lg[i]);
        smax = m;
    }
    __syncthreads();
    float e = 0.f;
    if (t < ASSETS) { e = expf(logit - smax); lg[t] = e; }
    __syncthreads();
    if (t == 0) {
        float s = 0.f;
        for (int i = 0; i < ASSETS; i++) s += lg[i];
        ssum = s;
    }
    __syncthreads();
    if (t < ASSETS) out[g * ASSETS + t] = lg[t] / ssum;
}

// ---------------- launch -----------------------------------------------------
extern "C" void kernel_launch(void* const* d_in, const int* in_sizes, int n_in,
                              void* d_out, int out_size) {
    const float* x       = (const float*)d_in[0];
    const int*   ei      = (const int*)d_in[1];
    const int*   batch   = (const int*)d_in[2];
    const float* w1_rel  = (const float*)d_in[3];
    const float* b1      = (const float*)d_in[4];
    const float* w1_root = (const float*)d_in[5];
    const float* w2_rel  = (const float*)d_in[6];
    const float* b2      = (const float*)d_in[7];
    const float* w2_root = (const float*)d_in[8];
    const float* fc1w    = (const float*)d_in[9];
    const float* fc1b    = (const float*)d_in[10];
    const float* fc2w    = (const float*)d_in[11];
    const float* fc2b    = (const float*)d_in[12];
    float*       out     = (float*)d_out;

    const int N = in_sizes[2];        // 100000
    const int E = in_sizes[1] / 2;    // 1600000
    const int* src = ei;
    const int* dst = ei + E;

    void *xh, *agg1h, *h1h, *agg2h;
    cudaGetSymbolAddress(&xh,    g_xh);
    cudaGetSymbolAddress(&agg1h, g_agg1h);
    cudaGetSymbolAddress(&h1h,   g_h1h);
    cudaGetSymbolAddress(&agg2h, g_agg2h);

    const int SMEM1 = 192 * (64  + 4) * 4;   // 52224 B
    const int SMEM2 = 192 * (128 + 4) * 4;   // 101376 B
    cudaFuncSetAttribute((const void*)gemm_dual_fp16<64, true, false>,
                         cudaFuncAttributeMaxDynamicSharedMemorySize, SMEM1);
    cudaFuncSetAttribute((const void*)gemm_dual_fp16<128, true, true>,
                         cudaFuncAttributeMaxDynamicSharedMemorySize, SMEM2);

    // ---- init + CSR build ----
    init_kernel<<<512, 256>>>((const float2*)x, N * 32, N);
    hist_kernel<<<(E + 255) / 256, 256>>>(dst, E);
    int nscan = (N + 1023) / 1024;
    scan_onepass<<<nscan, 256>>>(N, E, batch);
    fill_csr<<<(E + 255) / 256, 256>>>(src, dst, E);

    // ---- layer 1 ----
    int gblocks = (N * 32 + 255) / 256;
    gather64h<<<gblocks, 256>>>(N);

    int tiles = (N + 63) / 64;
    int grid = tiles < 296 ? tiles : 296;
    gemm_dual_fp16<64, true, false><<<grid, 256, SMEM1>>>(
        (const __half*)agg1h, (const __half*)xh, w1_rel, w1_root, b1,
        (__half2*)h1h, nullptr, N, tiles);

    // ---- layer 2 (pool fused into epilogue) ----
    gather128h<<<gblocks, 256>>>(N);

    gemm_dual_fp16<128, true, true><<<grid, 256, SMEM2>>>(
        (const __half*)agg2h, (const __half*)h1h, w2_rel, w2_root, b2,
        nullptr, batch, N, tiles);

    // ---- head ----
    head_kernel<<<GG, 128>>>(fc1w, fc1b, fc2w, fc2b, out);
}

// round 12
// speedup vs baseline: 1.6082x; 1.0662x over previous
#include <cuda_runtime.h>
#include <cuda_fp16.h>
#include <math.h>
#include <stdint.h>

#define NN 100000
#define GG 64
#define ASSETS 50
#define EMAX 1600000

// ---------------- scratch (device globals; no runtime allocation) ----------
__device__ __half2 g_xh   [(size_t)NN * 32];   // 12.8 MB (x fp16)
__device__ __half2 g_agg1h[(size_t)NN * 32];   // 12.8 MB (agg1 fp16)
__device__ __half2 g_h1h  [(size_t)NN * 64];   // 25.6 MB (h1 fp16)
__device__ __half2 g_agg2h[(size_t)NN * 64];   // 25.6 MB (agg2 fp16)
__device__ float g_sums[GG * 128];
__device__ int   g_gstart[GG];
__device__ int   g_gend[GG];
// CSR scratch
__device__ int g_deg[NN];
__device__ int g_off[NN + 1];
__device__ int g_cur[NN];
__device__ int g_partials[256];
__device__ int g_sedge[EMAX];

// ---------------- helpers ---------------------------------------------------
__device__ __forceinline__ void mma16(float* d, const uint32_t* a, const uint32_t* b) {
    asm volatile("mma.sync.aligned.m16n8k16.row.col.f32.f16.f16.f32 "
                 "{%0,%1,%2,%3}, {%4,%5,%6,%7}, {%8,%9}, {%0,%1,%2,%3};"
                 : "+f"(d[0]), "+f"(d[1]), "+f"(d[2]), "+f"(d[3])
                 : "r"(a[0]), "r"(a[1]), "r"(a[2]), "r"(a[3]),
                   "r"(b[0]), "r"(b[1]));
}

__device__ __forceinline__ void add2(float4& acc, uint2 u) {
    float2 lo = __half22float2(*(__half2*)&u.x);
    float2 hi = __half22float2(*(__half2*)&u.y);
    acc.x += lo.x; acc.y += lo.y; acc.z += hi.x; acc.w += hi.y;
}
__device__ __forceinline__ void add4(float4& l, float4& h, uint4 u) {
    float2 p0 = __half22float2(*(__half2*)&u.x);
    float2 p1 = __half22float2(*(__half2*)&u.y);
    float2 p2 = __half22float2(*(__half2*)&u.z);
    float2 p3 = __half22float2(*(__half2*)&u.w);
    l.x += p0.x; l.y += p0.y; l.z += p1.x; l.w += p1.y;
    h.x += p2.x; h.y += p2.y; h.z += p3.x; h.w += p3.y;
}

// ---------------- init: zero scratch + convert x -> fp16 ---------------------
__global__ void init_kernel(const float2* __restrict__ x, int n2, int N) {
    int i = blockIdx.x * blockDim.x + threadIdx.x;
    int stride = gridDim.x * blockDim.x;
    for (int j = i; j < n2; j += stride)
        g_xh[j] = __float22half2_rn(x[j]);
    for (int j = i; j < N; j += stride)
        g_deg[j] = 0;
    if (i < GG * 128) g_sums[i] = 0.f;
    if (i < GG) { g_gstart[i] = 0; g_gend[i] = 0; }
}

// ---------------- CSR build --------------------------------------------------
__global__ void hist_kernel(const int* __restrict__ dst, int E) {
    int i = blockIdx.x * blockDim.x + threadIdx.x;
    if (i < E) atomicAdd(&g_deg[dst[i]], 1);
}

__global__ void scan_local(int n) {
    __shared__ int sh[256];
    int t = threadIdx.x;
    int base = blockIdx.x * 1024 + t * 4;
    int v[4];
    #pragma unroll
    for (int i = 0; i < 4; i++) v[i] = (base + i < n) ? g_deg[base + i] : 0;
    int tsum = v[0] + v[1] + v[2] + v[3];
    sh[t] = tsum;
    __syncthreads();
    #pragma unroll
    for (int o = 1; o < 256; o <<= 1) {
        int x = (t >= o) ? sh[t - o] : 0;
        __syncthreads();
        sh[t] += x;
        __syncthreads();
    }
    int excl = sh[t] - tsum;
    if (t == 255) g_partials[blockIdx.x] = sh[255];
    int run = excl;
    #pragma unroll
    for (int i = 0; i < 4; i++) {
        if (base + i < n) { g_off[base + i] = run; run += v[i]; }
    }
}

__global__ void scan_partials(int nb) {
    __shared__ int sh[256];
    int t = threadIdx.x;
    int orig = (t < nb) ? g_partials[t] : 0;
    sh[t] = orig;
    __syncthreads();
    #pragma unroll
    for (int o = 1; o < 256; o <<= 1) {
        int x = (t >= o) ? sh[t - o] : 0;
        __syncthreads();
        sh[t] += x;
        __syncthreads();
    }
    if (t < nb) g_partials[t] = sh[t] - orig;
}

// also detects per-graph segment boundaries in sorted batch (exact counts)
__global__ void scan_add(int n, int E, const int* __restrict__ batch) {
    int i = blockIdx.x * blockDim.x + threadIdx.x;
    if (i < n) {
        int v = g_off[i] + g_partials[i >> 10];
        g_off[i] = v;
        g_cur[i] = v;
        int b = batch[i];
        if (i == 0 || batch[i - 1] != b) g_gstart[b] = i;
        if (i == n - 1 || batch[i + 1] != b) g_gend[b] = i + 1;
    }
    if (i == 0) g_off[n] = E;
}

__global__ void fill_csr(const int* __restrict__ src, const int* __restrict__ dst, int E) {
    int i = blockIdx.x * blockDim.x + threadIdx.x;
    if (i < E) {
        int slot = atomicAdd(&g_cur[dst[i]], 1);
        g_sedge[slot] = src[i];
    }
}

// ---------------- CSR gather aggregation (fp16, fp32 acc) --------------------
// Half-warp paired: lanes 0-15 and 16-31 process two different edges in the
// same instruction; 16 lanes cover a full row. 4 slots -> 8 edges in flight.
__global__ void gather64h(int N) {
    const uint2* feat = (const uint2*)g_xh;     // row = 16 uint2 = 128 B
    int gtid = blockIdx.x * blockDim.x + threadIdx.x;
    int node = gtid >> 5;
    int lane = gtid & 31;
    if (node >= N) return;
    int half = lane >> 4;
    int sub  = lane & 15;
    int beg = g_off[node];
    int end = g_off[node + 1];
    float4 a0 = make_float4(0.f, 0.f, 0.f, 0.f), a1 = a0, a2 = a0, a3 = a0;
    for (int b = beg; b < end; b += 32) {
        int m = min(32, end - b);
        int s = (lane < m) ? g_sedge[b + lane] : 0;
        int i = 0;
        for (; i + 8 <= m; i += 8) {
            int t0 = __shfl_sync(0xffffffffu, s, i     + half);
            int t1 = __shfl_sync(0xffffffffu, s, i + 2 + half);
            int t2 = __shfl_sync(0xffffffffu, s, i + 4 + half);
            int t3 = __shfl_sync(0xffffffffu, s, i + 6 + half);
            uint2 u0 = feat[(size_t)t0 * 16 + sub];
            uint2 u1 = feat[(size_t)t1 * 16 + sub];
            uint2 u2 = feat[(size_t)t2 * 16 + sub];
            uint2 u3 = feat[(size_t)t3 * 16 + sub];
            add2(a0, u0); add2(a1, u1); add2(a2, u2); add2(a3, u3);
        }
        for (; i + 2 <= m; i += 2) {
            int t0 = __shfl_sync(0xffffffffu, s, i + half);
            uint2 u0 = feat[(size_t)t0 * 16 + sub];
            add2(a0, u0);
        }
        if (i < m) {
            int t0 = __shfl_sync(0xffffffffu, s, i);   // all lanes converged
            if (half == 0) {
                uint2 u0 = feat[(size_t)t0 * 16 + sub];
                add2(a0, u0);
            }
        }
    }
    float4 r;
    r.x = (a0.x + a1.x) + (a2.x + a3.x);
    r.y = (a0.y + a1.y) + (a2.y + a3.y);
    r.z = (a0.z + a1.z) + (a2.z + a3.z);
    r.w = (a0.w + a1.w) + (a2.w + a3.w);
    // merge the two half-warp partial sums
    r.x += __shfl_down_sync(0xffffffffu, r.x, 16);
    r.y += __shfl_down_sync(0xffffffffu, r.y, 16);
    r.z += __shfl_down_sync(0xffffffffu, r.z, 16);
    r.w += __shfl_down_sync(0xffffffffu, r.w, 16);
    if (half == 0) {
        uint2 o;
        *(__half2*)&o.x = __float22half2_rn(make_float2(r.x, r.y));
        *(__half2*)&o.y = __float22half2_rn(make_float2(r.z, r.w));
        ((uint2*)g_agg1h)[(size_t)node * 16 + sub] = o;
    }
}

__global__ void gather128h(int N) {
    const uint4* feat = (const uint4*)g_h1h;    // row = 16 uint4 = 256 B
    int gtid = blockIdx.x * blockDim.x + threadIdx.x;
    int node = gtid >> 5;
    int lane = gtid & 31;
    if (node >= N) return;
    int half = lane >> 4;
    int sub  = lane & 15;
    int beg = g_off[node];
    int end = g_off[node + 1];
    float4 l0 = make_float4(0.f, 0.f, 0.f, 0.f), h0 = l0;
    float4 l1 = l0, h1 = l0, l2 = l0, h2 = l0, l3 = l0, h3 = l0;
    for (int b = beg; b < end; b += 32) {
        int m = min(32, end - b);
        int s = (lane < m) ? g_sedge[b + lane] : 0;
        int i = 0;
        for (; i + 8 <= m; i += 8) {
            int t0 = __shfl_sync(0xffffffffu, s, i     + half);
            int t1 = __shfl_sync(0xffffffffu, s, i + 2 + half);
            int t2 = __shfl_sync(0xffffffffu, s, i + 4 + half);
            int t3 = __shfl_sync(0xffffffffu, s, i + 6 + half);
            uint4 u0 = feat[(size_t)t0 * 16 + sub];
            uint4 u1 = feat[(size_t)t1 * 16 + sub];
            uint4 u2 = feat[(size_t)t2 * 16 + sub];
            uint4 u3 = feat[(size_t)t3 * 16 + sub];
            add4(l0, h0, u0); add4(l1, h1, u1);
            add4(l2, h2, u2); add4(l3, h3, u3);
        }
        for (; i + 2 <= m; i += 2) {
            int t0 = __shfl_sync(0xffffffffu, s, i + half);
            uint4 u0 = feat[(size_t)t0 * 16 + sub];
            add4(l0, h0, u0);
        }
        if (i < m) {
            int t0 = __shfl_sync(0xffffffffu, s, i);
            if (half == 0) {
                uint4 u0 = feat[(size_t)t0 * 16 + sub];
                add4(l0, h0, u0);
            }
        }
    }
    float4 rl, rh;
    rl.x = (l0.x + l1.x) + (l2.x + l3.x);
    rl.y = (l0.y + l1.y) + (l2.y + l3.y);
    rl.z = (l0.z + l1.z) + (l2.z + l3.z);
    rl.w = (l0.w + l1.w) + (l2.w + l3.w);
    rh.x = (h0.x + h1.x) + (h2.x + h3.x);
    rh.y = (h0.y + h1.y) + (h2.y + h3.y);
    rh.z = (h0.z + h1.z) + (h2.z + h3.z);
    rh.w = (h0.w + h1.w) + (h2.w + h3.w);
    rl.x += __shfl_down_sync(0xffffffffu, rl.x, 16);
    rl.y += __shfl_down_sync(0xffffffffu, rl.y, 16);
    rl.z += __shfl_down_sync(0xffffffffu, rl.z, 16);
    rl.w += __shfl_down_sync(0xffffffffu, rl.w, 16);
    rh.x += __shfl_down_sync(0xffffffffu, rh.x, 16);
    rh.y += __shfl_down_sync(0xffffffffu, rh.y, 16);
    rh.z += __shfl_down_sync(0xffffffffu, rh.z, 16);
    rh.w += __shfl_down_sync(0xffffffffu, rh.w, 16);
    if (half == 0) {
        uint4 o;
        *(__half2*)&o.x = __float22half2_rn(make_float2(rl.x, rl.y));
        *(__half2*)&o.y = __float22half2_rn(make_float2(rl.z, rl.w));
        *(__half2*)&o.z = __float22half2_rn(make_float2(rh.x, rh.y));
        *(__half2*)&o.w = __float22half2_rn(make_float2(rh.z, rh.w));
        ((uint4*)g_agg2h)[(size_t)node * 16 + sub] = o;
    }
}

// ---------------- fused dual GEMM (fp16 tensor cores) + bias + relu ----------
// POOL=true: epilogue does segmented mean-pool into g_sums (batch sorted).
template<int K, bool PF, bool POOL>
__global__ void __launch_bounds__(256)
gemm_dual_fp16(const __half* __restrict__ A, const __half* __restrict__ B,
               const float* __restrict__ wA, const float* __restrict__ wB,
               const float* __restrict__ bias, __half2* __restrict__ out,
               const int* __restrict__ batch, int N, int num_tiles) {
    constexpr int U   = K + 4;             // row stride in uint32
    constexpr int QP4 = K / 8;             // uint4 per row per matrix
    constexpr int PER = (64 * QP4) / 256;

    extern __shared__ uint32_t smem_u[];
    uint32_t* sW  = smem_u;                // [128][U]
    uint32_t* sIn = smem_u + 128 * U;      // [64][U]
    float*    sInF = (float*)sIn;          // aliased fp32 tile for pooling
    __shared__ int sb[64];

    const int tid  = threadIdx.x;
    const int lane = tid & 31;
    const int wid  = tid >> 5;
    const int wm   = wid & 1;
    const int wn   = wid >> 1;

    // stage weights once: fp32 gmem -> fp16 smem, transposed n-major
    {
        __half* sWh = (__half*)sW;
        for (int idx = tid; idx < K * 128; idx += 256) {
            int k = idx >> 7;
            int n = idx & 127;
            sWh[n * (2 * U) + k]     = __float2half_rn(wA[idx]);
            sWh[n * (2 * U) + K + k] = __float2half_rn(wB[idx]);
        }
    }

    uint4 pa[PER], pb[PER];

    auto loadTile = [&](int tile) {
        #pragma unroll
        for (int i = 0; i < PER; i++) {
            int idx = tid + i * 256;
            int r = idx / QP4, q = idx % QP4;
            int grow = tile * 64 + r;
            if (tile < num_tiles && grow < N) {
                pa[i] = ((const uint4*)(A + (size_t)grow * K))[q];
                pb[i] = ((const uint4*)(B + (size_t)grow * K))[q];
            } else {
                pa[i] = make_uint4(0u, 0u, 0u, 0u);
                pb[i] = pa[i];
            }
        }
    };
    auto storeTile = [&]() {
        #pragma unroll
        for (int i = 0; i < PER; i++) {
            int idx = tid + i * 256;
            int r = idx / QP4, q = idx % QP4;
            *(uint4*)&sIn[r * U + q * 4]            = pa[i];
            *(uint4*)&sIn[r * U + (K >> 1) + q * 4] = pb[i];
        }
    };

    loadTile(blockIdx.x);
    __syncthreads();
    storeTile();
    __syncthreads();

    const int fr = lane >> 2;
    const int fc = lane & 3;

    for (int tile = blockIdx.x; tile < num_tiles; tile += gridDim.x) {
        const int row0 = tile << 6;
        const int ntile = tile + gridDim.x;

        if (PF && ntile < num_tiles) loadTile(ntile);

        float acc[2][4][4] = {};
        const uint32_t* sInW = sIn + (wm * 32) * U;
        const uint32_t* sWW  = sW  + (wn * 32) * U;

        #pragma unroll 4
        for (int kw = 0; kw < K; kw += 8) {
            uint32_t a[2][4];
            #pragma unroll
            for (int mt = 0; mt < 2; mt++) {
                const uint32_t* p = sInW + (mt * 16 + fr) * U + kw + fc;
                a[mt][0] = p[0];
                a[mt][1] = p[8 * U];
                a[mt][2] = p[4];
                a[mt][3] = p[8 * U + 4];
            }
            uint32_t b[4][2];
            #pragma unroll
            for (int nt = 0; nt < 4; nt++) {
                const uint32_t* p = sWW + (nt * 8 + fr) * U + kw + fc;
                b[nt][0] = p[0];
                b[nt][1] = p[4];
            }
            #pragma unroll
            for (int mt = 0; mt < 2; mt++)
                #pragma unroll
                for (int nt = 0; nt < 4; nt++)
                    mma16(acc[mt][nt], a[mt], b[nt]);
        }

        __syncthreads();   // done reading sIn

        if (POOL) {
            if (tid < 64) {
                int rr = row0 + tid;
                sb[tid] = (rr < N) ? batch[rr] : -1;
            }
            #pragma unroll
            for (int mt = 0; mt < 2; mt++) {
                int lr = wm * 32 + mt * 16 + fr;
                #pragma unroll
                for (int nt = 0; nt < 4; nt++) {
                    int col = wn * 32 + nt * 8 + 2 * fc;
                    float2 bb = *(const float2*)&bias[col];
                    float2 o0, o1;
                    o0.x = fmaxf(acc[mt][nt][0] + bb.x, 0.f);
                    o0.y = fmaxf(acc[mt][nt][1] + bb.y, 0.f);
                    o1.x = fmaxf(acc[mt][nt][2] + bb.x, 0.f);
                    o1.y = fmaxf(acc[mt][nt][3] + bb.y, 0.f);
                    *(float2*)&sInF[lr * 130 + col]       = o0;
                    *(float2*)&sInF[(lr + 8) * 130 + col] = o1;
                }
            }
            __syncthreads();
            {
                int m = min(64, N - row0);
                int col  = tid & 127;
                int half = tid >> 7;
                int rs = half * 32;
                int re = min(m, rs + 32);
                if (rs < re) {
                    float acs = 0.f;
                    int cur = sb[rs];
                    for (int r = rs; r < re; r++) {
                        int g = sb[r];
                        float v = sInF[r * 130 + col];
                        if (g != cur) {
                            atomicAdd(&g_sums[cur * 128 + col], acs);
                            acs = 0.f; cur = g;
                        }
                        acs += v;
                    }
                    atomicAdd(&g_sums[cur * 128 + col], acs);
                }
            }
            __syncthreads();
            if (ntile < num_tiles) {
                if (!PF) loadTile(ntile);
                storeTile();
            }
            __syncthreads();
        } else {
            if (ntile < num_tiles) {
                if (!PF) loadTile(ntile);
                storeTile();
            }
            __syncthreads();
            #pragma unroll
            for (int mt = 0; mt < 2; mt++) {
                int r1 = row0 + wm * 32 + mt * 16 + fr;
                #pragma unroll
                for (int nt = 0; nt < 4; nt++) {
                    int col = wn * 32 + nt * 8 + 2 * fc;
                    float2 bb = *(const float2*)&bias[col];
                    if (r1 < N) {
                        float2 o;
                        o.x = fmaxf(acc[mt][nt][0] + bb.x, 0.f);
                        o.y = fmaxf(acc[mt][nt][1] + bb.y, 0.f);
                        out[(size_t)r1 * 64 + (col >> 1)] = __float22half2_rn(o);
                    }
                    if (r1 + 8 < N) {
                        float2 o;
                        o.x = fmaxf(acc[mt][nt][2] + bb.x, 0.f);
                        o.y = fmaxf(acc[mt][nt][3] + bb.y, 0.f);
                        out[(size_t)(r1 + 8) * 64 + (col >> 1)] = __float22half2_rn(o);
                    }
                }
            }
        }
    }
}

// ---------------- MLP head + softmax (one block per graph) -------------------
__global__ void head_kernel(const float* __restrict__ fc1w, const float* __restrict__ fc1b,
                            const float* __restrict__ fc2w, const float* __restrict__ fc2b,
                            float* __restrict__ out) {
    __shared__ float p[128];
    __shared__ float hdn[128];
    __shared__ float lg[ASSETS];
    __shared__ float smax, ssum;
    int g = blockIdx.x, t = threadIdx.x;

    float cnt = fmaxf((float)(g_gend[g] - g_gstart[g]), 1.f);
    p[t] = g_sums[g * 128 + t] / cnt;
    __syncthreads();

    float a = fc1b[t];
    #pragma unroll 8
    for (int k = 0; k < 128; k++) a = fmaf(p[k], fc1w[k * 128 + t], a);
    hdn[t] = fmaxf(a, 0.f);
    __syncthreads();

    float logit = 0.f;
    if (t < ASSETS) {
        logit = fc2b[t];
        #pragma unroll 8
        for (int k = 0; k < 128; k++) logit = fmaf(hdn[k], fc2w[k * ASSETS + t], logit);
        lg[t] = logit;
    }
    __syncthreads();
    if (t == 0) {
        float m = -1e30f;
        for (int i = 0; i < ASSETS; i++) m = fmaxf(m, lg[i]);
        smax = m;
    }
    __syncthreads();
    float e = 0.f;
    if (t < ASSETS) { e = expf(logit - smax); lg[t] = e; }
    __syncthreads();
    if (t == 0) {
        float s = 0.f;
        for (int i = 0; i < ASSETS; i++) s += lg[i];
        ssum = s;
    }
    __syncthreads();
    if (t < ASSETS) out[g * ASSETS + t] = lg[t] / ssum;
}

// ---------------- launch -----------------------------------------------------
extern "C" void kernel_launch(void* const* d_in, const int* in_sizes, int n_in,
                              void* d_out, int out_size) {
    const float* x       = (const float*)d_in[0];
    const int*   ei      = (const int*)d_in[1];
    const int*   batch   = (const int*)d_in[2];
    const float* w1_rel  = (const float*)d_in[3];
    const float* b1      = (const float*)d_in[4];
    const float* w1_root = (const float*)d_in[5];
    const float* w2_rel  = (const float*)d_in[6];
    const float* b2      = (const float*)d_in[7];
    const float* w2_root = (const float*)d_in[8];
    const float* fc1w    = (const float*)d_in[9];
    const float* fc1b    = (const float*)d_in[10];
    const float* fc2w    = (const float*)d_in[11];
    const float* fc2b    = (const float*)d_in[12];
    float*       out     = (float*)d_out;

    const int N = in_sizes[2];        // 100000
    const int E = in_sizes[1] / 2;    // 1600000
    const int* src = ei;
    const int* dst = ei + E;

    void *xh, *agg1h, *h1h, *agg2h;
    cudaGetSymbolAddress(&xh,    g_xh);
    cudaGetSymbolAddress(&agg1h, g_agg1h);
    cudaGetSymbolAddress(&h1h,   g_h1h);
    cudaGetSymbolAddress(&agg2h, g_agg2h);

    const int SMEM1 = 192 * (64  + 4) * 4;   // 52224 B
    const int SMEM2 = 192 * (128 + 4) * 4;   // 101376 B
    cudaFuncSetAttribute((const void*)gemm_dual_fp16<64, true, false>,
                         cudaFuncAttributeMaxDynamicSharedMemorySize, SMEM1);
    cudaFuncSetAttribute((const void*)gemm_dual_fp16<128, true, true>,
                         cudaFuncAttributeMaxDynamicSharedMemorySize, SMEM2);

    // ---- init + CSR build (3-kernel scan: proven fastest) ----
    init_kernel<<<512, 256>>>((const float2*)x, N * 32, N);
    hist_kernel<<<(E + 255) / 256, 256>>>(dst, E);
    int nscan = (N + 1023) / 1024;
    scan_local<<<nscan, 256>>>(N);
    scan_partials<<<1, 256>>>(nscan);
    scan_add<<<(N + 255) / 256, 256>>>(N, E, batch);
    fill_csr<<<(E + 255) / 256, 256>>>(src, dst, E);

    // ---- layer 1 ----
    int gblocks = (N * 32 + 255) / 256;
    gather64h<<<gblocks, 256>>>(N);

    int tiles = (N + 63) / 64;
    int grid = tiles < 296 ? tiles : 296;
    gemm_dual_fp16<64, true, false><<<grid, 256, SMEM1>>>(
        (const __half*)agg1h, (const __half*)xh, w1_rel, w1_root, b1,
        (__half2*)h1h, nullptr, N, tiles);

    // ---- layer 2 (pool fused into epilogue) ----
    gather128h<<<gblocks, 256>>>(N);

    gemm_dual_fp16<128, true, true><<<grid, 256, SMEM2>>>(
        (const __half*)agg2h, (const __half*)h1h, w2_rel, w2_root, b2,
        nullptr, batch, N, tiles);

    // ---- head ----
    head_kernel<<<GG, 128>>>(fc1w, fc1b, fc2w, fc2b, out);
}